// round 5
// baseline (speedup 1.0000x reference)
#include <cuda_runtime.h>
#include <cstdint>
#include <cstddef>

// Problem dims
#define T_DIM 1024
#define H_DIM 512
#define B_DIM 64
#define NM    18
#define NBLK  144
#define THR   256

// ---------------------------------------------------------------------------
// Device-global scratch (~20MB)
// ---------------------------------------------------------------------------
__device__ float g_Ut[NM * H_DIM * H_DIM];      // Ut[m][j][h] = U_m[h][j]
__device__ float g_l[B_DIM * 8 * H_DIM];        // l[b][k][h]
__device__ float g_f[B_DIM * H_DIM];            // f[b][h]
__device__ float g_o[B_DIM * H_DIM];            // o[b][h]
__device__ float g_hT[H_DIM * B_DIM];           // h transposed: hT[h][b]
__device__ unsigned g_flags[NBLK];
__device__ unsigned g_epoch;

// ---------------------------------------------------------------------------
// f32x2 helpers
// ---------------------------------------------------------------------------
__device__ __forceinline__ unsigned long long pack2(float v) {
    unsigned long long r;
    asm("mov.b64 %0, {%1, %1};" : "=l"(r) : "f"(v));
    return r;
}
__device__ __forceinline__ unsigned long long fma2(unsigned long long a,
                                                   unsigned long long b,
                                                   unsigned long long c) {
    unsigned long long d;
    asm("fma.rn.f32x2 %0, %1, %2, %3;" : "=l"(d) : "l"(a), "l"(b), "l"(c));
    return d;
}
__device__ __forceinline__ float2 unpack2(unsigned long long v) {
    float2 f;
    asm("mov.b64 {%0, %1}, %2;" : "=f"(f.x), "=f"(f.y) : "l"(v));
    return f;
}

__device__ __forceinline__ float fsig(float x) {
    x = fminf(fmaxf(x, -30.f), 30.f);
    return 1.f / (1.f + __expf(-x));
}
__device__ __forceinline__ float ftanh(float x) {
    x = fminf(fmaxf(x, -15.f), 15.f);
    float e = __expf(2.f * x);
    return (e - 1.f) / (e + 1.f);
}

struct Ptrs { const float* p[28]; };

__device__ __forceinline__ void matInfo(const Ptrs& P, int m,
                                        const float*& W, const float*& bias,
                                        const float*& X, int& C) {
    if (m < 4) {
        C = 8; X = P.p[0];
        W = P.p[8 + 3 * m]; bias = P.p[10 + 3 * m];
    } else if (m < 11) {
        int k = m - 4; C = 3;
        X = P.p[(k == 0) ? 1 : 2];                 // aux input gates: x1 then x2 (faithful quirk)
        W = P.p[20] + (size_t)k * 3 * H_DIM; bias = P.p[22] + (size_t)k * H_DIM;
    } else {
        int k = m - 11; C = 3;
        X = P.p[1 + k];                            // aux candidates: x1..x7
        W = P.p[23] + (size_t)k * 3 * H_DIM; bias = P.p[25] + (size_t)k * H_DIM;
    }
}

// ---------------------------------------------------------------------------
__global__ void reset_kernel() {
    int i = blockIdx.x * blockDim.x + threadIdx.x;
    int n = gridDim.x * blockDim.x;
    if (i == 0) g_epoch = 0u;
    if (i < NBLK) g_flags[i] = 0u;
    for (int k = i; k < H_DIM * B_DIM; k += n) g_hT[k] = 0.f;
}

// Ut[m][j][h] = U_m[h][j]   (m < 18 only; W_a used untransposed)
__global__ void transpose_kernel(Ptrs P) {
    int j = blockIdx.x, m = blockIdx.y;
    const float* U;
    if (m < 4)        U = P.p[9 + 3 * m];
    else if (m < 11)  U = P.p[21] + (size_t)(m - 4)  * H_DIM * H_DIM;
    else              U = P.p[24] + (size_t)(m - 11) * H_DIM * H_DIM;
    for (int h = threadIdx.x; h < H_DIM; h += blockDim.x)
        g_Ut[((size_t)m * H_DIM + j) * H_DIM + h] = U[(size_t)h * H_DIM + j];
}

// ---------------------------------------------------------------------------
// Flag-array epoch grid barrier, pure spin (no nanosleep).
// ---------------------------------------------------------------------------
__device__ __forceinline__ void grid_barrier(unsigned target) {
    __syncthreads();
    if (threadIdx.x == 0) {
        __threadfence();
        *(volatile unsigned*)&g_flags[blockIdx.x] = target;
    }
    if (blockIdx.x == 0) {
        if (threadIdx.x < NBLK) {
            while (*(volatile unsigned*)&g_flags[threadIdx.x] < target) { }
        }
        __syncthreads();
        if (threadIdx.x == 0) {
            __threadfence();
            *(volatile unsigned*)&g_epoch = target;
        }
    }
    if (threadIdx.x == 0) {
        while (*(volatile unsigned*)&g_epoch < target) { }
        __threadfence();
    }
    __syncthreads();
}

// ---------------------------------------------------------------------------
// Persistent recurrent kernel, 144 CTAs x 256 threads.
//
// Phase A: z = x@W + b + h@U for 18 matrices, fused gate pairs.
//   cta = p*16 + bg*8 + jb : p<9 pair, bg<2 (32 batches), jb<8 (64 j).
//   thread = bq(4: 8 batches) x jloc(64). K-chunked (2 x 256 h) via smem.
// Phase B: a[b][k][g] = sum_h l[b][k][h] W_a[h][g] ; softmax combine.
//   cta<128 = bt(8: 8 b) x gt(16: 32 g); thread = bloc(8) x gloc(32),
//   owns one (b,g) for all t (c kept in register). l K-chunked (4 x 128 h).
// ---------------------------------------------------------------------------
__global__ void __launch_bounds__(THR, 1)
main_kernel(Ptrs P, float* __restrict__ out) {
    __shared__ __align__(16) float2 sh2[4096];     // 32KB, reused A/B
    __shared__ float shxA[32 * 8];
    __shared__ float shxB[32 * 8];

    const int cta = blockIdx.x, tid = threadIdx.x;

    // --- phase A ids ---
    const int p    = cta >> 4;            // 0..8
    const int bg   = (cta >> 3) & 1;      // 0..1
    const int jb   = cta & 7;             // 0..7
    const int jloc = tid & 63;
    const int bq   = tid >> 6;            // 0..3
    const int j    = jb * 64 + jloc;
    const int bbase = bg * 32;
    int ma, mb;
    if      (p == 0) { ma = 0; mb = 2; }
    else if (p == 1) { ma = 1; mb = 3; }
    else             { ma = 4 + (p - 2); mb = 11 + (p - 2); }

    const float *WA, *WB, *bAp, *bBp, *XA, *XB;
    int Ca, Cb;
    matInfo(P, ma, WA, bAp, XA, Ca);
    matInfo(P, mb, WB, bBp, XB, Cb);
    float wA[8], wB[8];
    #pragma unroll
    for (int c = 0; c < 8; c++) { wA[c] = 0.f; wB[c] = 0.f; }
    for (int c = 0; c < Ca; c++) wA[c] = WA[(size_t)c * H_DIM + j];
    for (int c = 0; c < Cb; c++) wB[c] = WB[(size_t)c * H_DIM + j];
    const float bA = bAp[j], bB = bBp[j];
    const float4* UA4 = (const float4*)(g_Ut + ((size_t)ma * H_DIM + j) * H_DIM);
    const float4* UB4 = (const float4*)(g_Ut + ((size_t)mb * H_DIM + j) * H_DIM);

    // --- phase B ids ---
    const int btB   = cta >> 4;           // 0..7 (valid for cta<128)
    const int gtB   = cta & 15;
    const int blocB = tid >> 5;           // 0..7
    const int glocB = tid & 31;
    const int bB_   = btB * 8 + blocB;
    const int gB    = gtB * 32 + glocB;
    const float* W_a = P.p[26];
    const float  baB = P.p[27][gB & (H_DIM - 1)];
    float c_reg = 0.f;

    union F4 { float4 v; float f[4]; };

    for (int t = 0; t < T_DIM; t++) {
        // =============== Phase A ===============
        unsigned long long accA[4], accB[4];
        #pragma unroll
        for (int i = 0; i < 4; i++) { accA[i] = 0ull; accB[i] = 0ull; }

        #pragma unroll
        for (int ck = 0; ck < 2; ck++) {
            // stage h chunk: sh2[hh_l*16 + bp] = (h[2bp], h[2bp+1]) for our 32 batches
            for (int i = tid; i < 4096; i += THR) {
                int hh_l = i >> 4, bp = i & 15;
                sh2[i] = __ldcg((const float2*)&g_hT[(ck * 256 + hh_l) * B_DIM + bbase + 2 * bp]);
            }
            if (ck == 0) {
                // stage this step's raw inputs (32 batches)
                for (int i = tid; i < 32 * Ca; i += THR) {
                    int b = i / Ca, c = i - b * Ca;
                    shxA[b * 8 + c] = XA[((size_t)(bbase + b) * Ca + c) * T_DIM + t];
                }
                for (int i = tid; i < 32 * Cb; i += THR) {
                    int b = i / Cb, c = i - b * Cb;
                    shxB[b * 8 + c] = XB[((size_t)(bbase + b) * Cb + c) * T_DIM + t];
                }
            }
            __syncthreads();

            const ulonglong2* shv = (const ulonglong2*)sh2;
            #pragma unroll 2
            for (int hb = 0; hb < 64; hb++) {
                F4 ua, ub;
                ua.v = UA4[ck * 64 + hb];
                ub.v = UB4[ck * 64 + hb];
                #pragma unroll
                for (int q = 0; q < 4; q++) {
                    int hh_l = hb * 4 + q;
                    unsigned long long ua2 = pack2(ua.f[q]);
                    unsigned long long ub2 = pack2(ub.f[q]);
                    ulonglong2 h0 = shv[hh_l * 8 + bq * 2 + 0];   // batches bq*8+0..3
                    ulonglong2 h1 = shv[hh_l * 8 + bq * 2 + 1];   // batches bq*8+4..7
                    accA[0] = fma2(h0.x, ua2, accA[0]);
                    accA[1] = fma2(h0.y, ua2, accA[1]);
                    accA[2] = fma2(h1.x, ua2, accA[2]);
                    accA[3] = fma2(h1.y, ua2, accA[3]);
                    accB[0] = fma2(h0.x, ub2, accB[0]);
                    accB[1] = fma2(h0.y, ub2, accB[1]);
                    accB[2] = fma2(h1.x, ub2, accB[2]);
                    accB[3] = fma2(h1.y, ub2, accB[3]);
                }
            }
            __syncthreads();
        }

        // epilogue: input proj + activations + stores (8 batches)
        #pragma unroll
        for (int i = 0; i < 4; i++) {
            int bl0 = bq * 8 + 2 * i, bl1 = bl0 + 1;
            float pa0 = bA, pa1 = bA, pb0 = bB, pb1 = bB;
            for (int c = 0; c < Ca; c++) {
                pa0 = fmaf(shxA[bl0 * 8 + c], wA[c], pa0);
                pa1 = fmaf(shxA[bl1 * 8 + c], wA[c], pa1);
            }
            for (int c = 0; c < Cb; c++) {
                pb0 = fmaf(shxB[bl0 * 8 + c], wB[c], pb0);
                pb1 = fmaf(shxB[bl1 * 8 + c], wB[c], pb1);
            }
            float2 a2 = unpack2(accA[i]);
            float2 b2 = unpack2(accB[i]);
            float za0 = a2.x + pa0, za1 = a2.y + pa1;
            float zb0 = b2.x + pb0, zb1 = b2.y + pb1;
            int b0 = bbase + bl0, b1 = bbase + bl1;
            if (p == 1) {
                g_f[b0 * H_DIM + j] = fsig(za0);
                g_f[b1 * H_DIM + j] = fsig(za1);
                g_o[b0 * H_DIM + j] = fsig(zb0);
                g_o[b1 * H_DIM + j] = fsig(zb1);
            } else {
                int k = (p == 0) ? 0 : (p - 1);
                g_l[(b0 * 8 + k) * H_DIM + j] = fsig(za0) * ftanh(zb0);
                g_l[(b1 * 8 + k) * H_DIM + j] = fsig(za1) * ftanh(zb1);
            }
        }

        grid_barrier(2 * t + 1);

        // =============== Phase B ===============
        if (cta < 128) {
            unsigned long long acc[4] = {0ull, 0ull, 0ull, 0ull};
            float lg[8];

            #pragma unroll
            for (int ck = 0; ck < 4; ck++) {
                // stage l chunk: sh2[(q*8+bl)*256 + hh_l*2 + k2b] = (l[4q+2k2b], l[4q+2k2b+1]) at hh
                for (int i = tid; i < 4096; i += THR) {
                    int hh_l = i & 127;
                    int rr = i >> 7;
                    int k2b = rr & 1;
                    int bl = (rr >> 1) & 7;
                    int q  = rr >> 4;
                    int k2 = q * 2 + k2b;
                    const float* src = &g_l[(((btB * 8 + bl) * 8 + 2 * k2) * H_DIM) + ck * 128 + hh_l];
                    float v0 = __ldcg(src);
                    float v1 = __ldcg(src + H_DIM);
                    sh2[(q * 8 + bl) * 256 + hh_l * 2 + k2b] = make_float2(v0, v1);
                }
                __syncthreads();

                const ulonglong2* shv = (const ulonglong2*)sh2;
                if ((gB >> 7) == ck) {       // capture l[b][k][g] while resident
                    int hl = gB & 127;
                    ulonglong2 v0 = shv[(0 * 8 + blocB) * 128 + hl];
                    ulonglong2 v1 = shv[(1 * 8 + blocB) * 128 + hl];
                    float2 q2;
                    q2 = unpack2(v0.x); lg[0] = q2.x; lg[1] = q2.y;
                    q2 = unpack2(v0.y); lg[2] = q2.x; lg[3] = q2.y;
                    q2 = unpack2(v1.x); lg[4] = q2.x; lg[5] = q2.y;
                    q2 = unpack2(v1.y); lg[6] = q2.x; lg[7] = q2.y;
                }

                #pragma unroll 4
                for (int hh_l = 0; hh_l < 128; hh_l++) {
                    int hh = ck * 128 + hh_l;
                    unsigned long long w2 = pack2(__ldcg(&W_a[(size_t)hh * H_DIM + gB]));
                    ulonglong2 v0 = shv[(0 * 8 + blocB) * 128 + hh_l];
                    ulonglong2 v1 = shv[(1 * 8 + blocB) * 128 + hh_l];
                    acc[0] = fma2(v0.x, w2, acc[0]);
                    acc[1] = fma2(v0.y, w2, acc[1]);
                    acc[2] = fma2(v1.x, w2, acc[2]);
                    acc[3] = fma2(v1.y, w2, acc[3]);
                }
                __syncthreads();
            }

            float a[8];
            { float2 q2;
              q2 = unpack2(acc[0]); a[0] = q2.x; a[1] = q2.y;
              q2 = unpack2(acc[1]); a[2] = q2.x; a[3] = q2.y;
              q2 = unpack2(acc[2]); a[4] = q2.x; a[5] = q2.y;
              q2 = unpack2(acc[3]); a[6] = q2.x; a[7] = q2.y; }

            float u[8], mx = -1e30f;
            #pragma unroll
            for (int k = 0; k < 8; k++) {
                u[k] = ftanh(fmaf(a[k], c_reg, baB));
                mx = fmaxf(mx, u[k]);
            }
            float es = 0.f, L = 0.f;
            #pragma unroll
            for (int k = 0; k < 8; k++) {
                float e = __expf(u[k] - mx);
                es += e;
                L  += e * lg[k];
            }
            L /= es;
            int idx = bB_ * H_DIM + gB;
            float fv = __ldcg(&g_f[idx]);
            float ov = __ldcg(&g_o[idx]);
            c_reg = fmaf(fv, c_reg, L);
            float hn = ov * ftanh(c_reg);
            g_hT[gB * B_DIM + bB_] = hn;
            out[(size_t)B_DIM * H_DIM + ((size_t)bB_ * T_DIM + t) * H_DIM + gB] = hn;
            if (t == T_DIM - 1) out[(size_t)bB_ * H_DIM + gB] = hn;
        }

        grid_barrier(2 * t + 2);
    }
}

// ---------------------------------------------------------------------------
extern "C" void kernel_launch(void* const* d_in, const int* in_sizes, int n_in,
                              void* d_out, int out_size) {
    (void)in_sizes; (void)n_in; (void)out_size;
    Ptrs P;
    for (int i = 0; i < 28; i++) P.p[i] = (const float*)d_in[i];

    reset_kernel<<<64, 256>>>();
    transpose_kernel<<<dim3(H_DIM, NM), 128>>>(P);
    main_kernel<<<NBLK, THR>>>(P, (float*)d_out);
}

// round 6
// speedup vs baseline: 1.8147x; 1.8147x over previous
#include <cuda_runtime.h>
#include <cstdint>
#include <cstddef>

// Problem dims
#define T_DIM 1024
#define H_DIM 512
#define B_DIM 64
#define NBLK  144
#define THR   256

// ---------------------------------------------------------------------------
// Device-global scratch (~1.2MB)
// ---------------------------------------------------------------------------
__device__ float g_l[B_DIM * 8 * H_DIM];        // l[b][k][h]
__device__ float g_f[B_DIM * H_DIM];            // f[b][h]
__device__ float g_o[B_DIM * H_DIM];            // o[b][h]
__device__ float g_hT[H_DIM * B_DIM];           // h transposed: hT[h][b]
__device__ unsigned g_flags[NBLK];
__device__ unsigned g_epoch;

// ---------------------------------------------------------------------------
// f32x2 helpers
// ---------------------------------------------------------------------------
__device__ __forceinline__ unsigned long long pack2(float v) {
    unsigned long long r;
    asm("mov.b64 %0, {%1, %1};" : "=l"(r) : "f"(v));
    return r;
}
__device__ __forceinline__ unsigned long long fma2(unsigned long long a,
                                                   unsigned long long b,
                                                   unsigned long long c) {
    unsigned long long d;
    asm("fma.rn.f32x2 %0, %1, %2, %3;" : "=l"(d) : "l"(a), "l"(b), "l"(c));
    return d;
}
__device__ __forceinline__ float2 unpack2(unsigned long long v) {
    float2 f;
    asm("mov.b64 {%0, %1}, %2;" : "=f"(f.x), "=f"(f.y) : "l"(v));
    return f;
}

__device__ __forceinline__ float fsig(float x) {
    x = fminf(fmaxf(x, -30.f), 30.f);
    return 1.f / (1.f + __expf(-x));
}
__device__ __forceinline__ float ftanh(float x) {
    x = fminf(fmaxf(x, -15.f), 15.f);
    float e = __expf(2.f * x);
    return (e - 1.f) / (e + 1.f);
}

struct Ptrs { const float* p[28]; };

// Input-projection metadata for matrix m.
__device__ __forceinline__ void matInfo(const Ptrs& P, int m,
                                        const float*& W, const float*& bias,
                                        const float*& X, int& C) {
    if (m < 4) {
        C = 8; X = P.p[0];
        W = P.p[8 + 3 * m]; bias = P.p[10 + 3 * m];
    } else if (m < 11) {
        int k = m - 4; C = 3;
        X = P.p[(k == 0) ? 1 : 2];                 // aux input gates: x1 then x2 (faithful quirk)
        W = P.p[20] + (size_t)k * 3 * H_DIM; bias = P.p[22] + (size_t)k * H_DIM;
    } else {
        int k = m - 11; C = 3;
        X = P.p[1 + k];                            // aux candidates: x1..x7
        W = P.p[23] + (size_t)k * 3 * H_DIM; bias = P.p[25] + (size_t)k * H_DIM;
    }
}
// Recurrent matrix U_m base pointer (ORIGINAL [h][j] layout — no transpose).
__device__ __forceinline__ const float* Uptr(const Ptrs& P, int m) {
    if (m < 4)  return P.p[9 + 3 * m];
    if (m < 11) return P.p[21] + (size_t)(m - 4)  * H_DIM * H_DIM;
    return             P.p[24] + (size_t)(m - 11) * H_DIM * H_DIM;
}

// ---------------------------------------------------------------------------
__global__ void reset_kernel() {
    int i = blockIdx.x * blockDim.x + threadIdx.x;
    int n = gridDim.x * blockDim.x;
    if (i == 0) g_epoch = 0u;
    if (i < NBLK) g_flags[i] = 0u;
    for (int k = i; k < H_DIM * B_DIM; k += n) g_hT[k] = 0.f;
}

// ---------------------------------------------------------------------------
// Flag-array epoch grid barrier.
// ---------------------------------------------------------------------------
__device__ __forceinline__ void grid_barrier(unsigned target) {
    __syncthreads();
    if (threadIdx.x == 0) {
        __threadfence();
        *(volatile unsigned*)&g_flags[blockIdx.x] = target;
    }
    if (blockIdx.x == 0) {
        if (threadIdx.x < NBLK) {
            while (*(volatile unsigned*)&g_flags[threadIdx.x] < target) __nanosleep(64);
        }
        __syncthreads();
        if (threadIdx.x == 0) {
            __threadfence();
            *(volatile unsigned*)&g_epoch = target;
        }
    }
    if (threadIdx.x == 0) {
        while (*(volatile unsigned*)&g_epoch < target) __nanosleep(64);
        __threadfence();
    }
    __syncthreads();
}

// ---------------------------------------------------------------------------
// Shared memory union (static, 43KB)
// ---------------------------------------------------------------------------
union SmemU {
    struct {
        float4 U[2 * 64 * 16];     // 32KB: [mat][hh_l][f4]  (64 j per row)
        float2 H[64 * 16];         // 8KB : [hh_l][bp]  (32 batches as 16 pairs)
        float  xA[32 * 8];
        float  xB[32 * 8];
    } a;
    struct {
        float2 L[2048];            // 16KB: [(q*8+bl)*128 + hh_l*2 + k2b]
        float  W[64 * 32];         // 8KB : [hh_l][gloc]
    } b;
};

// ---------------------------------------------------------------------------
// Persistent recurrent kernel, 144 CTAs x 256 threads.
// Phase A: cta = p*16 + bg*8 + jb ; thread = bq(4) x jloc(64).
//   K-chunked 8 x 64h; U staged coalesced to smem each chunk.
// Phase B (cta<128): cta = bt(8) x gt(16); thread = bloc(8) x gloc(32);
//   owns one (b,g), c in register. K-chunked 8 x 64h; l + W_a staged to smem.
// ---------------------------------------------------------------------------
__global__ void __launch_bounds__(THR, 1)
main_kernel(Ptrs P, float* __restrict__ out) {
    __shared__ __align__(16) SmemU sm;

    const int cta = blockIdx.x, tid = threadIdx.x;

    // --- phase A ids ---
    const int p    = cta >> 4;
    const int bg   = (cta >> 3) & 1;
    const int jb   = cta & 7;
    const int jloc = tid & 63;
    const int bq   = tid >> 6;
    const int j    = jb * 64 + jloc;
    const int bbase = bg * 32;
    int ma, mb;
    if      (p == 0) { ma = 0; mb = 2; }
    else if (p == 1) { ma = 1; mb = 3; }
    else             { ma = 4 + (p - 2); mb = 11 + (p - 2); }

    const float *WA, *WB, *bAp, *bBp, *XA, *XB;
    int Ca, Cb;
    matInfo(P, ma, WA, bAp, XA, Ca);
    matInfo(P, mb, WB, bBp, XB, Cb);
    float wA[8], wB[8];
    #pragma unroll
    for (int c = 0; c < 8; c++) { wA[c] = 0.f; wB[c] = 0.f; }
    for (int c = 0; c < Ca; c++) wA[c] = WA[(size_t)c * H_DIM + j];
    for (int c = 0; c < Cb; c++) wB[c] = WB[(size_t)c * H_DIM + j];
    const float bA = bAp[j], bB = bBp[j];
    const float* Ua_p = Uptr(P, ma) + jb * 64;     // row h contiguous in j
    const float* Ub_p = Uptr(P, mb) + jb * 64;

    // --- phase B ids ---
    const int btB   = cta >> 4;
    const int gtB   = cta & 15;
    const int blocB = tid >> 5;
    const int glocB = tid & 31;
    const int bB_   = btB * 8 + blocB;
    const int gB    = gtB * 32 + glocB;
    const float* W_a = P.p[26] + gtB * 32;
    const float  baB = P.p[27][(gtB * 32 + glocB) & (H_DIM - 1)];
    float c_reg = 0.f;

    for (int t = 0; t < T_DIM; t++) {
        // =============== Phase A ===============
        unsigned long long accA[4], accB[4];
        #pragma unroll
        for (int i = 0; i < 4; i++) { accA[i] = 0ull; accB[i] = 0ull; }

        #pragma unroll 1
        for (int ck = 0; ck < 8; ck++) {
            // stage U chunk coalesced: 2 mats x 64 rows x 16 float4
            #pragma unroll
            for (int r = 0; r < 8; r++) {
                int i = tid + r * THR;                  // 0..2047
                int mat = i >> 10, rr = i & 1023;
                int hh_l = rr >> 4, f4 = rr & 15;
                const float* base = mat ? Ub_p : Ua_p;
                sm.a.U[i] = __ldcg((const float4*)(base + (size_t)(ck * 64 + hh_l) * H_DIM) + f4);
            }
            // stage h chunk: [hh_l][bp] float2, coalesced
            #pragma unroll
            for (int r = 0; r < 4; r++) {
                int i = tid + r * THR;                  // 0..1023
                int hh_l = i >> 4, bp = i & 15;
                sm.a.H[i] = __ldcg((const float2*)&g_hT[(ck * 64 + hh_l) * B_DIM + bbase + 2 * bp]);
            }
            if (ck == 0) {
                for (int i = tid; i < 32 * Ca; i += THR) {
                    int b = i / Ca, c = i - b * Ca;
                    sm.a.xA[b * 8 + c] = XA[((size_t)(bbase + b) * Ca + c) * T_DIM + t];
                }
                for (int i = tid; i < 32 * Cb; i += THR) {
                    int b = i / Cb, c = i - b * Cb;
                    sm.a.xB[b * 8 + c] = XB[((size_t)(bbase + b) * Cb + c) * T_DIM + t];
                }
            }
            __syncthreads();

            const float* shUf = (const float*)sm.a.U;
            const ulonglong2* shHv = (const ulonglong2*)sm.a.H;   // 8 per row
            #pragma unroll 4
            for (int hh_l = 0; hh_l < 64; hh_l++) {
                float ua = shUf[hh_l * 64 + jloc];
                float ub = shUf[4096 + hh_l * 64 + jloc];
                unsigned long long ua2 = pack2(ua);
                unsigned long long ub2 = pack2(ub);
                ulonglong2 h0 = shHv[hh_l * 8 + bq * 2 + 0];
                ulonglong2 h1 = shHv[hh_l * 8 + bq * 2 + 1];
                accA[0] = fma2(h0.x, ua2, accA[0]);
                accA[1] = fma2(h0.y, ua2, accA[1]);
                accA[2] = fma2(h1.x, ua2, accA[2]);
                accA[3] = fma2(h1.y, ua2, accA[3]);
                accB[0] = fma2(h0.x, ub2, accB[0]);
                accB[1] = fma2(h0.y, ub2, accB[1]);
                accB[2] = fma2(h1.x, ub2, accB[2]);
                accB[3] = fma2(h1.y, ub2, accB[3]);
            }
            __syncthreads();
        }

        // epilogue: input projections + activations + stores (8 batches)
        #pragma unroll
        for (int i = 0; i < 4; i++) {
            int bl0 = bq * 8 + 2 * i, bl1 = bl0 + 1;
            float pa0 = bA, pa1 = bA, pb0 = bB, pb1 = bB;
            for (int c = 0; c < Ca; c++) {
                pa0 = fmaf(sm.a.xA[bl0 * 8 + c], wA[c], pa0);
                pa1 = fmaf(sm.a.xA[bl1 * 8 + c], wA[c], pa1);
            }
            for (int c = 0; c < Cb; c++) {
                pb0 = fmaf(sm.a.xB[bl0 * 8 + c], wB[c], pb0);
                pb1 = fmaf(sm.a.xB[bl1 * 8 + c], wB[c], pb1);
            }
            float2 a2 = unpack2(accA[i]);
            float2 b2 = unpack2(accB[i]);
            float za0 = a2.x + pa0, za1 = a2.y + pa1;
            float zb0 = b2.x + pb0, zb1 = b2.y + pb1;
            int b0 = bbase + bl0, b1 = bbase + bl1;
            if (p == 1) {
                g_f[b0 * H_DIM + j] = fsig(za0);
                g_f[b1 * H_DIM + j] = fsig(za1);
                g_o[b0 * H_DIM + j] = fsig(zb0);
                g_o[b1 * H_DIM + j] = fsig(zb1);
            } else {
                int k = (p == 0) ? 0 : (p - 1);
                g_l[(b0 * 8 + k) * H_DIM + j] = fsig(za0) * ftanh(zb0);
                g_l[(b1 * 8 + k) * H_DIM + j] = fsig(za1) * ftanh(zb1);
            }
        }

        grid_barrier(2 * t + 1);

        // =============== Phase B ===============
        if (cta < 128) {
            unsigned long long acc[4] = {0ull, 0ull, 0ull, 0ull};
            float lg[8];

            #pragma unroll 1
            for (int ck = 0; ck < 8; ck++) {
                // stage l chunk: 2048 float2, coalesced in hh
                #pragma unroll
                for (int r = 0; r < 8; r++) {
                    int i = tid + r * THR;
                    int hh_l = i & 63;
                    int rr = i >> 6;
                    int k2b = rr & 1;
                    int bl = (rr >> 1) & 7;
                    int q  = rr >> 4;
                    const float* src = &g_l[(((btB * 8 + bl) * 8 + 2 * (q * 2 + k2b)) << 9)
                                            + ck * 64 + hh_l];
                    sm.b.L[(q * 8 + bl) * 128 + hh_l * 2 + k2b] =
                        make_float2(__ldcg(src), __ldcg(src + H_DIM));
                }
                // stage W_a chunk: 64 rows x 8 float4, coalesced
                #pragma unroll
                for (int r = 0; r < 2; r++) {
                    int i = tid + r * THR;
                    int hh_l = i >> 3, f4 = i & 7;
                    ((float4*)sm.b.W)[i] =
                        __ldcg((const float4*)(W_a + (size_t)(ck * 64 + hh_l) * H_DIM) + f4);
                }
                __syncthreads();

                const ulonglong2* shLv = (const ulonglong2*)sm.b.L;
                if ((gB >> 6) == ck) {           // capture l[b][*][gB] while resident
                    int hl = gB & 63;
                    ulonglong2 v0 = shLv[blocB * 64 + hl];
                    ulonglong2 v1 = shLv[(8 + blocB) * 64 + hl];
                    float2 q2;
                    q2 = unpack2(v0.x); lg[0] = q2.x; lg[1] = q2.y;
                    q2 = unpack2(v0.y); lg[2] = q2.x; lg[3] = q2.y;
                    q2 = unpack2(v1.x); lg[4] = q2.x; lg[5] = q2.y;
                    q2 = unpack2(v1.y); lg[6] = q2.x; lg[7] = q2.y;
                }

                #pragma unroll 4
                for (int hh_l = 0; hh_l < 64; hh_l++) {
                    unsigned long long w2 = pack2(sm.b.W[hh_l * 32 + glocB]);
                    ulonglong2 v0 = shLv[blocB * 64 + hh_l];
                    ulonglong2 v1 = shLv[(8 + blocB) * 64 + hh_l];
                    acc[0] = fma2(v0.x, w2, acc[0]);
                    acc[1] = fma2(v0.y, w2, acc[1]);
                    acc[2] = fma2(v1.x, w2, acc[2]);
                    acc[3] = fma2(v1.y, w2, acc[3]);
                }
                __syncthreads();
            }

            float a[8];
            { float2 q2;
              q2 = unpack2(acc[0]); a[0] = q2.x; a[1] = q2.y;
              q2 = unpack2(acc[1]); a[2] = q2.x; a[3] = q2.y;
              q2 = unpack2(acc[2]); a[4] = q2.x; a[5] = q2.y;
              q2 = unpack2(acc[3]); a[6] = q2.x; a[7] = q2.y; }

            float u[8], mx = -1e30f;
            #pragma unroll
            for (int k = 0; k < 8; k++) {
                u[k] = ftanh(fmaf(a[k], c_reg, baB));
                mx = fmaxf(mx, u[k]);
            }
            float es = 0.f, L = 0.f;
            #pragma unroll
            for (int k = 0; k < 8; k++) {
                float e = __expf(u[k] - mx);
                es += e;
                L  += e * lg[k];
            }
            L /= es;
            int idx = bB_ * H_DIM + gB;
            float fv = __ldcg(&g_f[idx]);
            float ov = __ldcg(&g_o[idx]);
            c_reg = fmaf(fv, c_reg, L);
            float hn = ov * ftanh(c_reg);
            g_hT[gB * B_DIM + bB_] = hn;
            out[(size_t)B_DIM * H_DIM + ((size_t)bB_ * T_DIM + t) * H_DIM + gB] = hn;
            if (t == T_DIM - 1) out[(size_t)bB_ * H_DIM + gB] = hn;
        }

        grid_barrier(2 * t + 2);
    }
}

// ---------------------------------------------------------------------------
extern "C" void kernel_launch(void* const* d_in, const int* in_sizes, int n_in,
                              void* d_out, int out_size) {
    (void)in_sizes; (void)n_in; (void)out_size;
    Ptrs P;
    for (int i = 0; i < 28; i++) P.p[i] = (const float*)d_in[i];

    reset_kernel<<<64, 256>>>();
    main_kernel<<<NBLK, THR>>>(P, (float*)d_out);
}

// round 7
// speedup vs baseline: 1.9000x; 1.0470x over previous
#include <cuda_runtime.h>
#include <cstdint>
#include <cstddef>

// Problem dims
#define T_DIM 1024
#define H_DIM 512
#define B_DIM 64
#define NBLK  144
#define THR   512
#define DYN_SMEM (84 * 1024)

// ---------------------------------------------------------------------------
// Device-global scratch (~1.2MB)
// ---------------------------------------------------------------------------
__device__ float g_l[B_DIM * 8 * H_DIM];        // l[b][k][h]
__device__ float g_f[B_DIM * H_DIM];            // f[b][h]
__device__ float g_o[B_DIM * H_DIM];            // o[b][h]
__device__ float g_hT[H_DIM * B_DIM];           // h transposed: hT[h][b]
__device__ unsigned g_flags[NBLK];
__device__ unsigned g_epoch;

// ---------------------------------------------------------------------------
// f32x2 helpers
// ---------------------------------------------------------------------------
__device__ __forceinline__ unsigned long long pack2(float v) {
    unsigned long long r;
    asm("mov.b64 %0, {%1, %1};" : "=l"(r) : "f"(v));
    return r;
}
__device__ __forceinline__ unsigned long long fma2(unsigned long long a,
                                                   unsigned long long b,
                                                   unsigned long long c) {
    unsigned long long d;
    asm("fma.rn.f32x2 %0, %1, %2, %3;" : "=l"(d) : "l"(a), "l"(b), "l"(c));
    return d;
}
__device__ __forceinline__ float2 unpack2(unsigned long long v) {
    float2 f;
    asm("mov.b64 {%0, %1}, %2;" : "=f"(f.x), "=f"(f.y) : "l"(v));
    return f;
}

__device__ __forceinline__ float fsig(float x) {
    x = fminf(fmaxf(x, -30.f), 30.f);
    return 1.f / (1.f + __expf(-x));
}
__device__ __forceinline__ float ftanh(float x) {
    x = fminf(fmaxf(x, -15.f), 15.f);
    float e = __expf(2.f * x);
    return (e - 1.f) / (e + 1.f);
}

struct Ptrs { const float* p[28]; };

// Input-projection metadata for matrix m.
__device__ __forceinline__ void matInfo(const Ptrs& P, int m,
                                        const float*& W, const float*& bias,
                                        const float*& X, int& C) {
    if (m < 4) {
        C = 8; X = P.p[0];
        W = P.p[8 + 3 * m]; bias = P.p[10 + 3 * m];
    } else if (m < 11) {
        int k = m - 4; C = 3;
        X = P.p[(k == 0) ? 1 : 2];                 // aux input gates: x1 then x2 (faithful quirk)
        W = P.p[20] + (size_t)k * 3 * H_DIM; bias = P.p[22] + (size_t)k * H_DIM;
    } else {
        int k = m - 11; C = 3;
        X = P.p[1 + k];                            // aux candidates: x1..x7
        W = P.p[23] + (size_t)k * 3 * H_DIM; bias = P.p[25] + (size_t)k * H_DIM;
    }
}
// Recurrent matrix U_m base pointer (ORIGINAL [h][j] layout).
__device__ __forceinline__ const float* Uptr(const Ptrs& P, int m) {
    if (m < 4)  return P.p[9 + 3 * m];
    if (m < 11) return P.p[21] + (size_t)(m - 4)  * H_DIM * H_DIM;
    return             P.p[24] + (size_t)(m - 11) * H_DIM * H_DIM;
}

// ---------------------------------------------------------------------------
__global__ void reset_kernel() {
    int i = blockIdx.x * blockDim.x + threadIdx.x;
    int n = gridDim.x * blockDim.x;
    if (i == 0) g_epoch = 0u;
    if (i < NBLK) g_flags[i] = 0u;
    for (int k = i; k < H_DIM * B_DIM; k += n) g_hT[k] = 0.f;
}

// ---------------------------------------------------------------------------
// Flag-array epoch grid barrier.
// ---------------------------------------------------------------------------
__device__ __forceinline__ void grid_barrier(unsigned target) {
    __syncthreads();
    if (threadIdx.x == 0) {
        __threadfence();
        *(volatile unsigned*)&g_flags[blockIdx.x] = target;
    }
    if (blockIdx.x == 0) {
        if (threadIdx.x < NBLK) {
            while (*(volatile unsigned*)&g_flags[threadIdx.x] < target) __nanosleep(64);
        }
        __syncthreads();
        if (threadIdx.x == 0) {
            __threadfence();
            *(volatile unsigned*)&g_epoch = target;
        }
    }
    if (threadIdx.x == 0) {
        while (*(volatile unsigned*)&g_epoch < target) __nanosleep(64);
        __threadfence();
    }
    __syncthreads();
}

// ---------------------------------------------------------------------------
// Persistent recurrent kernel, 144 CTAs x 512 threads, 84KB dynamic smem.
//
// Phase A: cta = p*16 + bg*8 + jb ; thread = bq(8: 4 batches) x jloc(64).
//   K-chunked 8 x 64h, double-buffered smem staging (U + h).
// Phase B (cta<128): cta = bt(8) x gt(16); thread = kh(2: gate halves)
//   x bloc(8) x gloc(32). Each (b,g) split across 2 threads by gate index;
//   merged via smem exchange. c kept in kh=0 thread's register.
// ---------------------------------------------------------------------------
__global__ void __launch_bounds__(THR, 1)
main_kernel(Ptrs P, float* __restrict__ out) {
    extern __shared__ __align__(16) char dyn[];
    // phase A layout
    float*  sU  = (float*)dyn;                    // [2][2*64*64]   64KB
    float2* sH  = (float2*)(dyn + 65536);         // [2][64*16]     16KB
    float*  sxA = (float*)(dyn + 81920);          // [256]           1KB
    float*  sxB = (float*)(dyn + 82944);          // [256]           1KB
    // phase B overlay
    float2* sL  = (float2*)dyn;                   // [2][8*64*4]    32KB
    float*  sW  = (float*)(dyn + 32768);          // [2][64*32]     16KB
    float*  sE  = (float*)(dyn + 49152);          // [256*8]         8KB

    const int cta = blockIdx.x, tid = threadIdx.x;

    // --- phase A ids ---
    const int p    = cta >> 4;
    const int bg   = (cta >> 3) & 1;
    const int jb   = cta & 7;
    const int jloc = tid & 63;
    const int bq   = tid >> 6;                 // 0..7, 4 batches each
    const int j    = jb * 64 + jloc;
    const int bbase = bg * 32;
    int ma, mb;
    if      (p == 0) { ma = 0; mb = 2; }
    else if (p == 1) { ma = 1; mb = 3; }
    else             { ma = 4 + (p - 2); mb = 11 + (p - 2); }

    const float *WA, *WB, *bAp, *bBp, *XA, *XB;
    int Ca, Cb;
    matInfo(P, ma, WA, bAp, XA, Ca);
    matInfo(P, mb, WB, bBp, XB, Cb);
    float wA[8], wB[8];
    #pragma unroll
    for (int c = 0; c < 8; c++) { wA[c] = 0.f; wB[c] = 0.f; }
    for (int c = 0; c < Ca; c++) wA[c] = WA[(size_t)c * H_DIM + j];
    for (int c = 0; c < Cb; c++) wB[c] = WB[(size_t)c * H_DIM + j];
    const float bA = bAp[j], bB = bBp[j];
    const float* Ua_p = Uptr(P, ma) + jb * 64;
    const float* Ub_p = Uptr(P, mb) + jb * 64;

    // --- phase B ids ---
    const int btB   = cta >> 4;                // 0..7 (cta<128)
    const int gtB   = cta & 15;
    const int kh    = tid >> 8;                // 0..1 gate half
    const int rB    = tid & 255;
    const int blocB = rB >> 5;                 // 0..7
    const int glocB = rB & 31;
    const int bB_   = btB * 8 + blocB;
    const int gB    = gtB * 32 + glocB;
    const float* W_a = P.p[26] + gtB * 32;
    const float  baB = P.p[27][gB & (H_DIM - 1)];
    float c_reg = 0.f;

    float4 uR[4]; float2 hR[2];
    float2 lR[4]; float4 wR;

#define LD_A(ck) do { \
    _Pragma("unroll") \
    for (int r = 0; r < 4; r++) { int i = tid + r * THR; \
        int mat = i >> 10, rr = i & 1023, hh = rr >> 4, f4 = rr & 15; \
        const float* base = mat ? Ub_p : Ua_p; \
        uR[r] = __ldg((const float4*)(base + (size_t)((ck) * 64 + hh) * H_DIM) + f4); } \
    _Pragma("unroll") \
    for (int r = 0; r < 2; r++) { int i = tid + r * THR; \
        int hh = i >> 4, bp = i & 15; \
        hR[r] = __ldcg((const float2*)&g_hT[((ck) * 64 + hh) * B_DIM + bbase + 2 * bp]); } \
} while (0)
#define ST_A(buf) do { \
    _Pragma("unroll") \
    for (int r = 0; r < 4; r++) { int i = tid + r * THR; \
        ((float4*)(sU + (buf) * 8192))[i] = uR[r]; } \
    _Pragma("unroll") \
    for (int r = 0; r < 2; r++) { int i = tid + r * THR; \
        (sH + (buf) * 1024)[i] = hR[r]; } \
} while (0)
#define LD_B(ck) do { \
    _Pragma("unroll") \
    for (int r = 0; r < 4; r++) { int i = tid + r * THR; \
        int hh = i & 63, rr = i >> 6, k2 = rr & 3, bl = rr >> 2; \
        const float* src = &g_l[(((btB * 8 + bl) * 8 + 2 * k2) << 9) + (ck) * 64 + hh]; \
        lR[r] = make_float2(__ldcg(src), __ldcg(src + H_DIM)); } \
    { int hh = tid >> 3, f4 = tid & 7; \
      wR = __ldg((const float4*)(W_a + (size_t)((ck) * 64 + hh) * H_DIM) + f4); } \
} while (0)
#define ST_B(buf) do { \
    _Pragma("unroll") \
    for (int r = 0; r < 4; r++) { int i = tid + r * THR; \
        int hh = i & 63, rr = i >> 6, k2 = rr & 3, bl = rr >> 2; \
        (sL + (buf) * 2048)[(bl * 64 + hh) * 4 + k2] = lR[r]; } \
    { ((float4*)(sW + (buf) * 2048))[tid] = wR; } \
} while (0)

    for (int t = 0; t < T_DIM; t++) {
        // =============== Phase A ===============
        unsigned long long accA[2], accB[2];
        accA[0] = accA[1] = accB[0] = accB[1] = 0ull;

        LD_A(0);
        for (int i = tid; i < 32 * Ca; i += THR) {
            int b = i / Ca, c = i - b * Ca;
            sxA[b * 8 + c] = XA[((size_t)(bbase + b) * Ca + c) * T_DIM + t];
        }
        for (int i = tid; i < 32 * Cb; i += THR) {
            int b = i / Cb, c = i - b * Cb;
            sxB[b * 8 + c] = XB[((size_t)(bbase + b) * Cb + c) * T_DIM + t];
        }
        ST_A(0);
        __syncthreads();

        #pragma unroll 1
        for (int ck = 0; ck < 8; ck++) {
            if (ck < 7) LD_A(ck + 1);
            const float* U0 = sU + (ck & 1) * 8192;
            const ulonglong2* Hv = (const ulonglong2*)(sH + (ck & 1) * 1024);
            #pragma unroll 4
            for (int hh = 0; hh < 64; hh++) {
                unsigned long long ua2 = pack2(U0[hh * 64 + jloc]);
                unsigned long long ub2 = pack2(U0[4096 + hh * 64 + jloc]);
                ulonglong2 hv = Hv[hh * 8 + bq];
                accA[0] = fma2(hv.x, ua2, accA[0]);
                accA[1] = fma2(hv.y, ua2, accA[1]);
                accB[0] = fma2(hv.x, ub2, accB[0]);
                accB[1] = fma2(hv.y, ub2, accB[1]);
            }
            if (ck < 7) { __syncthreads(); ST_A((ck + 1) & 1); __syncthreads(); }
        }

        // epilogue: input projections + activations + stores (4 batches)
        #pragma unroll
        for (int q = 0; q < 2; q++) {
            int bl0 = bq * 4 + 2 * q, bl1 = bl0 + 1;
            float pa0 = bA, pa1 = bA, pb0 = bB, pb1 = bB;
            for (int c = 0; c < Ca; c++) {
                pa0 = fmaf(sxA[bl0 * 8 + c], wA[c], pa0);
                pa1 = fmaf(sxA[bl1 * 8 + c], wA[c], pa1);
            }
            for (int c = 0; c < Cb; c++) {
                pb0 = fmaf(sxB[bl0 * 8 + c], wB[c], pb0);
                pb1 = fmaf(sxB[bl1 * 8 + c], wB[c], pb1);
            }
            float2 a2 = unpack2(accA[q]);
            float2 b2 = unpack2(accB[q]);
            float za0 = a2.x + pa0, za1 = a2.y + pa1;
            float zb0 = b2.x + pb0, zb1 = b2.y + pb1;
            int b0 = bbase + bl0, b1 = bbase + bl1;
            if (p == 1) {
                g_f[b0 * H_DIM + j] = fsig(za0);
                g_f[b1 * H_DIM + j] = fsig(za1);
                g_o[b0 * H_DIM + j] = fsig(zb0);
                g_o[b1 * H_DIM + j] = fsig(zb1);
            } else {
                int k = (p == 0) ? 0 : (p - 1);
                g_l[(b0 * 8 + k) * H_DIM + j] = fsig(za0) * ftanh(zb0);
                g_l[(b1 * 8 + k) * H_DIM + j] = fsig(za1) * ftanh(zb1);
            }
        }

        grid_barrier(2 * t + 1);

        // =============== Phase B ===============
        if (cta < 128) {
            unsigned long long acc[2] = {0ull, 0ull};
            float lgh[4];

            LD_B(0); ST_B(0); __syncthreads();

            #pragma unroll 1
            for (int ck = 0; ck < 8; ck++) {
                if (ck < 7) LD_B(ck + 1);
                const float* W0 = sW + (ck & 1) * 2048;
                const ulonglong2* Lv = (const ulonglong2*)(sL + (ck & 1) * 2048);
                if ((gB >> 6) == ck) {
                    ulonglong2 v = Lv[(blocB * 64 + (gB & 63)) * 2 + kh];
                    float2 q2;
                    q2 = unpack2(v.x); lgh[0] = q2.x; lgh[1] = q2.y;
                    q2 = unpack2(v.y); lgh[2] = q2.x; lgh[3] = q2.y;
                }
                #pragma unroll 8
                for (int hh = 0; hh < 64; hh++) {
                    unsigned long long w2 = pack2(W0[hh * 32 + glocB]);
                    ulonglong2 lv = Lv[(blocB * 64 + hh) * 2 + kh];
                    acc[0] = fma2(lv.x, w2, acc[0]);
                    acc[1] = fma2(lv.y, w2, acc[1]);
                }
                if (ck < 7) { __syncthreads(); ST_B((ck + 1) & 1); __syncthreads(); }
            }

            float ah[4];
            { float2 q2;
              q2 = unpack2(acc[0]); ah[0] = q2.x; ah[1] = q2.y;
              q2 = unpack2(acc[1]); ah[2] = q2.x; ah[3] = q2.y; }

            if (kh == 1) {
                #pragma unroll
                for (int q = 0; q < 4; q++) {
                    sE[rB * 8 + q]     = ah[q];
                    sE[rB * 8 + 4 + q] = lgh[q];
                }
            }
            __syncthreads();
            if (kh == 0) {
                float a[8], lg[8];
                #pragma unroll
                for (int q = 0; q < 4; q++) {
                    a[q]      = ah[q];
                    lg[q]     = lgh[q];
                    a[4 + q]  = sE[rB * 8 + q];
                    lg[4 + q] = sE[rB * 8 + 4 + q];
                }
                float u[8], mx = -1e30f;
                #pragma unroll
                for (int k = 0; k < 8; k++) {
                    u[k] = ftanh(fmaf(a[k], c_reg, baB));
                    mx = fmaxf(mx, u[k]);
                }
                float es = 0.f, L = 0.f;
                #pragma unroll
                for (int k = 0; k < 8; k++) {
                    float e = __expf(u[k] - mx);
                    es += e;
                    L  += e * lg[k];
                }
                L /= es;
                int idx = bB_ * H_DIM + gB;
                float fv = __ldcg(&g_f[idx]);
                float ov = __ldcg(&g_o[idx]);
                c_reg = fmaf(fv, c_reg, L);
                float hn = ov * ftanh(c_reg);
                g_hT[gB * B_DIM + bB_] = hn;
                out[(size_t)B_DIM * H_DIM + ((size_t)bB_ * T_DIM + t) * H_DIM + gB] = hn;
                if (t == T_DIM - 1) out[bB_ * H_DIM + gB] = hn;
            }
        }

        grid_barrier(2 * t + 2);
    }
#undef LD_A
#undef ST_A
#undef LD_B
#undef ST_B
}

// ---------------------------------------------------------------------------
extern "C" void kernel_launch(void* const* d_in, const int* in_sizes, int n_in,
                              void* d_out, int out_size) {
    (void)in_sizes; (void)n_in; (void)out_size;
    Ptrs P;
    for (int i = 0; i < 28; i++) P.p[i] = (const float*)d_in[i];

    cudaFuncSetAttribute(main_kernel,
                         cudaFuncAttributeMaxDynamicSharedMemorySize, DYN_SMEM);

    reset_kernel<<<64, 256>>>();
    main_kernel<<<NBLK, THR, DYN_SMEM>>>(P, (float*)d_out);
}